// round 4
// baseline (speedup 1.0000x reference)
#include <cuda_runtime.h>
#include <math.h>

#define B_  2
#define C_  512
#define N_  4096
#define E_  512
#define NH  8
#define HD  64

typedef unsigned long long u64;

// Scratch for projected Q/K/V in [b*NH+h][t][d] layout (head-major).
__device__ float g_Q[(size_t)B_ * NH * N_ * HD];
__device__ float g_K[(size_t)B_ * NH * N_ * HD];
__device__ float g_V[(size_t)B_ * NH * N_ * HD];

// ---- packed f32x2 helpers (Blackwell FFMA2 path) -------------------------
__device__ __forceinline__ u64 bcast2(float x) {
    u64 r; asm("mov.b64 %0, {%1, %1};" : "=l"(r) : "f"(x)); return r;
}
__device__ __forceinline__ float2 unpack2(u64 v) {
    float2 f; asm("mov.b64 {%0, %1}, %2;" : "=f"(f.x), "=f"(f.y) : "l"(v)); return f;
}
__device__ __forceinline__ void fma2(u64& d, u64 a, u64 b) {
    asm("fma.rn.f32x2 %0, %1, %2, %0;" : "+l"(d) : "l"(a), "l"(b));
}
__device__ __forceinline__ void mul2(u64& d, u64 a) {
    asm("mul.rn.f32x2 %0, %0, %1;" : "+l"(d) : "l"(a));
}

// 16B-chunk XOR swizzle for transposed [d][q] tiles (64 x 128 floats).
__device__ __forceinline__ int QSW(int d, int q) {
    return d * 128 + (((((q) >> 2) ^ ((d >> 2) & 7)) << 2) | (q & 3));
}

// Vt swizzle: [d][k] 64x128, 8B(u64)-chunk XOR keyed so that reads
// (d = 2*lane, 2*lane+1 at fixed even k) are conflict-free per 16-lane phase.
__device__ __forceinline__ int VSW(int d, int k) {
    int c = k >> 1;
    int cs = (c & ~15) | ((c ^ ((d >> 1) & 15)) & 15);
    return d * 128 + (cs << 1) + (k & 1);
}

// ---------------------------------------------------------------------------
// Projection: out[b, t, e] = sum_c X[b, c, t] * W[e, c] + bias[e]
// ---------------------------------------------------------------------------
__global__ __launch_bounds__(256) void proj_kernel(
    const float* __restrict__ q_in, const float* __restrict__ k_in,
    const float* __restrict__ Wq, const float* __restrict__ bq,
    const float* __restrict__ Wk, const float* __restrict__ bk,
    const float* __restrict__ Wv, const float* __restrict__ bv)
{
    __shared__ float Xs[32 * 128];   // [c][t]
    __shared__ float Wt[32 * 65];    // [c][e] transposed, pad 65

    int z = blockIdx.z;
    int proj = z >> 1, b = z & 1;

    const float* X = (proj == 0) ? q_in : k_in;
    const float* W; const float* bias; float* outp;
    if (proj == 0)      { W = Wq; bias = bq; outp = g_Q; }
    else if (proj == 1) { W = Wk; bias = bk; outp = g_K; }
    else                { W = Wv; bias = bv; outp = g_V; }

    int t0 = blockIdx.x * 128;
    int e0 = blockIdx.y * 64;
    int tid = threadIdx.x;
    int tx = tid & 15, ty = tid >> 4;

    u64 acc[4][4];
    #pragma unroll
    for (int p = 0; p < 4; p++)
        #pragma unroll
        for (int j = 0; j < 4; j++) acc[p][j] = 0ull;

    const float* Xb = X + (size_t)b * C_ * N_;

    for (int c0 = 0; c0 < C_; c0 += 32) {
        {   int c = tid >> 5, t4 = (tid & 31) * 4;
            #pragma unroll
            for (int cc = 0; cc < 32; cc += 8)
                *(float4*)&Xs[(c + cc) * 128 + t4] =
                    *(const float4*)&Xb[(size_t)(c0 + c + cc) * N_ + t0 + t4];
        }
        {   int e = tid >> 3, c4 = (tid & 7) * 4;
            #pragma unroll
            for (int ee = 0; ee < 64; ee += 32) {
                float4 w = *(const float4*)&W[(size_t)(e0 + e + ee) * C_ + c0 + c4];
                Wt[(c4 + 0) * 65 + e + ee] = w.x;
                Wt[(c4 + 1) * 65 + e + ee] = w.y;
                Wt[(c4 + 2) * 65 + e + ee] = w.z;
                Wt[(c4 + 3) * 65 + e + ee] = w.w;
            }
        }
        __syncthreads();

        #pragma unroll 4
        for (int c = 0; c < 32; c++) {
            ulonglong2 xa = *(const ulonglong2*)&Xs[c * 128 + ty * 8];
            ulonglong2 xb2 = *(const ulonglong2*)&Xs[c * 128 + ty * 8 + 4];
            u64 tp[4] = { xa.x, xa.y, xb2.x, xb2.y };
            #pragma unroll
            for (int j = 0; j < 4; j++) {
                u64 wb = bcast2(Wt[c * 65 + tx + 16 * j]);
                #pragma unroll
                for (int p = 0; p < 4; p++) fma2(acc[p][j], tp[p], wb);
            }
        }
        __syncthreads();
    }

    int head = blockIdx.y;
    float* ob = outp + (size_t)(b * NH + head) * N_ * HD;
    #pragma unroll
    for (int j = 0; j < 4; j++) {
        int d = tx + 16 * j;
        float bj = bias[e0 + d];
        #pragma unroll
        for (int p = 0; p < 4; p++) {
            float2 f = unpack2(acc[p][j]);
            int t = t0 + ty * 8 + 2 * p;
            ob[(size_t)t * HD + d]       = f.x + bj;
            ob[(size_t)(t + 1) * HD + d] = f.y + bj;
        }
    }
}

// ---------------------------------------------------------------------------
// Flash-style causal attention, 128x128 tiles, 512 threads, FFMA2.
// S phase:  thread (sx 0..15, sy 0..31): 4 q-rows (2 pairs) x 8 k-cols.
// PV phase: thread (px 0..31, py 0..15): 8 q-rows x 2 d (k-paired horiz acc).
// corr / l handed between layouts via smem arrays.
// ---------------------------------------------------------------------------
__global__ __launch_bounds__(512, 1) void attn_kernel(float* __restrict__ out)
{
    extern __shared__ float sm[];
    float* Qt   = sm;                    // 64*128 swizzled [d][q]
    float* Kt   = Qt + 64 * 128;         // 64*128 swizzled [d][k]
    float* Vt   = Kt + 64 * 128;         // 64*128 VSW [d][k]
    float* Ps   = Vt + 64 * 128;         // 128*128 natural [q][k]; reused as Osm[q*67+d]
    float* csm  = Ps + 128 * 128;        // corr[128]
    float* lsm  = csm + 128;             // l[128]

    int qtile = (int)gridDim.x - 1 - (int)blockIdx.x;   // heaviest first
    int bh = blockIdx.y;
    int q0 = qtile * 128;
    int tid = threadIdx.x;

    int sx = tid & 15, sy = tid >> 4;    // S/softmax layout
    int px = tid & 31, py = tid >> 5;    // PV layout
    int lr = tid >> 4, ld4 = (tid & 15) * 4;   // loader layout

    const float* Qg = g_Q + (size_t)bh * N_ * HD;
    const float* Kg = g_K + (size_t)bh * N_ * HD;
    const float* Vg = g_V + (size_t)bh * N_ * HD;

    // load + transpose Q (swizzled)
    #pragma unroll
    for (int rr = 0; rr < 128; rr += 32) {
        int r = lr + rr;
        float4 v = *(const float4*)&Qg[(size_t)(q0 + r) * HD + ld4];
        Qt[QSW(ld4 + 0, r)] = v.x; Qt[QSW(ld4 + 1, r)] = v.y;
        Qt[QSW(ld4 + 2, r)] = v.z; Qt[QSW(ld4 + 3, r)] = v.w;
    }

    float m[4], l[4];                    // softmax state for rows 4*sy + j
    u64 op2[8][2];                       // PV acc: rows 8*py+r, d = 2*px / 2*px+1
    #pragma unroll
    for (int j = 0; j < 4; j++) { m[j] = -1e30f; l[j] = 0.f; }
    #pragma unroll
    for (int r = 0; r < 8; r++) { op2[r][0] = 0ull; op2[r][1] = 0ull; }

    for (int kt = 0; kt <= qtile; kt++) {
        int k0 = kt * 128;
        __syncthreads();                 // previous iteration fully done
        #pragma unroll
        for (int rr = 0; rr < 128; rr += 32) {
            int r = lr + rr;
            float4 kv = *(const float4*)&Kg[(size_t)(k0 + r) * HD + ld4];
            Kt[QSW(ld4 + 0, r)] = kv.x; Kt[QSW(ld4 + 1, r)] = kv.y;
            Kt[QSW(ld4 + 2, r)] = kv.z; Kt[QSW(ld4 + 3, r)] = kv.w;
            float4 vv = *(const float4*)&Vg[(size_t)(k0 + r) * HD + ld4];
            Vt[VSW(ld4 + 0, r)] = vv.x; Vt[VSW(ld4 + 1, r)] = vv.y;
            Vt[VSW(ld4 + 2, r)] = vv.z; Vt[VSW(ld4 + 3, r)] = vv.w;
        }
        __syncthreads();

        // ---- S = Q K^T : 2 q-pairs x 8 k-cols per thread ----
        u64 s2[2][8];
        #pragma unroll
        for (int p = 0; p < 2; p++)
            #pragma unroll
            for (int c = 0; c < 8; c++) s2[p][c] = 0ull;

        #pragma unroll 2
        for (int d = 0; d < 64; d++) {
            int xd = (d >> 2) & 7;
            ulonglong2 qa = *(const ulonglong2*)&Qt[d * 128 + ((sy ^ xd) << 2)];
            float4 ka = *(const float4*)&Kt[d * 128 + (((2 * sx) ^ xd) << 2)];
            float4 kb = *(const float4*)&Kt[d * 128 + (((2 * sx + 1) ^ xd) << 2)];
            float kv[8] = { ka.x, ka.y, ka.z, ka.w, kb.x, kb.y, kb.z, kb.w };
            #pragma unroll
            for (int c = 0; c < 8; c++) {
                u64 kk = bcast2(kv[c]);
                fma2(s2[0][c], qa.x, kk);
                fma2(s2[1][c], qa.y, kk);
            }
        }

        // ---- softmax (rows 4*sy .. 4*sy+3), 16-lane reductions ----
        bool diag = (kt == qtile);
        #pragma unroll
        for (int p = 0; p < 2; p++) {
            float lo[8], hi[8];
            #pragma unroll
            for (int c = 0; c < 8; c++) {
                float2 f = unpack2(s2[p][c]);
                lo[c] = f.x * 0.125f;            // 1/sqrt(64)
                hi[c] = f.y * 0.125f;
            }
            int jl = 2 * p, jh = 2 * p + 1;
            int rl = 4 * sy + jl;                // local q rows
            if (diag) {
                int ql = q0 + rl;
                #pragma unroll
                for (int c = 0; c < 8; c++) {
                    int k = k0 + 8 * sx + c;
                    if (k > ql)     lo[c] = -1e9f;
                    if (k > ql + 1) hi[c] = -1e9f;
                }
            }
            float mtl = lo[0], mth = hi[0];
            #pragma unroll
            for (int c = 1; c < 8; c++) { mtl = fmaxf(mtl, lo[c]); mth = fmaxf(mth, hi[c]); }
            #pragma unroll
            for (int o = 1; o < 16; o <<= 1) {
                mtl = fmaxf(mtl, __shfl_xor_sync(0xffffffffu, mtl, o));
                mth = fmaxf(mth, __shfl_xor_sync(0xffffffffu, mth, o));
            }
            float mnl = fmaxf(m[jl], mtl);
            float mnh = fmaxf(m[jh], mth);
            float sl = 0.f, sh = 0.f;
            #pragma unroll
            for (int c = 0; c < 8; c++) {
                lo[c] = __expf(lo[c] - mnl); sl += lo[c];
                hi[c] = __expf(hi[c] - mnh); sh += hi[c];
            }
            #pragma unroll
            for (int o = 1; o < 16; o <<= 1) {
                sl += __shfl_xor_sync(0xffffffffu, sl, o);
                sh += __shfl_xor_sync(0xffffffffu, sh, o);
            }
            float cl = __expf(m[jl] - mnl);
            float ch = __expf(m[jh] - mnh);
            l[jl] = l[jl] * cl + sl;  m[jl] = mnl;
            l[jh] = l[jh] * ch + sh;  m[jh] = mnh;
            if (sx == 0) { csm[rl] = cl; csm[rl + 1] = ch; }

            *(float4*)&Ps[rl * 128 + 8 * sx]           = make_float4(lo[0], lo[1], lo[2], lo[3]);
            *(float4*)&Ps[rl * 128 + 8 * sx + 4]       = make_float4(lo[4], lo[5], lo[6], lo[7]);
            *(float4*)&Ps[(rl + 1) * 128 + 8 * sx]     = make_float4(hi[0], hi[1], hi[2], hi[3]);
            *(float4*)&Ps[(rl + 1) * 128 + 8 * sx + 4] = make_float4(hi[4], hi[5], hi[6], hi[7]);
        }
        __syncthreads();

        // ---- O += P @ V : k-paired, horizontal accumulation ----
        #pragma unroll
        for (int r = 0; r < 8; r++) {
            u64 c2 = bcast2(csm[8 * py + r]);
            mul2(op2[r][0], c2);
            mul2(op2[r][1], c2);
        }
        int vrow0 = (2 * px) * 128, vrow1 = (2 * px + 1) * 128;
        int vx = px & 15;
        #pragma unroll 2
        for (int k2 = 0; k2 < 64; k2++) {
            int k = 2 * k2;
            int cs = ((k2 & ~15) | ((k2 ^ vx) & 15)) << 1;
            u64 v0 = *(const u64*)&Vt[vrow0 + cs];
            u64 v1 = *(const u64*)&Vt[vrow1 + cs];
            #pragma unroll
            for (int r = 0; r < 8; r++) {
                u64 pp = *(const u64*)&Ps[(8 * py + r) * 128 + k];
                fma2(op2[r][0], pp, v0);
                fma2(op2[r][1], pp, v1);
            }
        }
    }

    // stage l, then epilogue
    if (sx == 0) {
        #pragma unroll
        for (int j = 0; j < 4; j++) lsm[4 * sy + j] = l[j];
    }
    __syncthreads();

    float* Osm = Ps;                     // reuse as [q][67]
    #pragma unroll
    for (int r = 0; r < 8; r++) {
        int row = 8 * py + r;
        float inv = 1.f / lsm[row];
        float2 a0 = unpack2(op2[r][0]);
        float2 a1 = unpack2(op2[r][1]);
        Osm[row * 67 + 2 * px]     = (a0.x + a0.y) * inv;
        Osm[row * 67 + 2 * px + 1] = (a1.x + a1.y) * inv;
    }
    __syncthreads();

    int b = bh >> 3, h = bh & 7;
    float* ob = out + ((size_t)b * E_ + (size_t)h * HD) * N_;
    for (int idx = tid; idx < 64 * 128; idx += 512) {
        int d = idx >> 7, q = idx & 127;
        ob[(size_t)d * N_ + q0 + q] = Osm[q * 67 + d];
    }
}

// ---------------------------------------------------------------------------

extern "C" void kernel_launch(void* const* d_in, const int* in_sizes, int n_in,
                              void* d_out, int out_size)
{
    const float* q_in = (const float*)d_in[0];
    const float* k_in = (const float*)d_in[1];
    const float* Wq   = (const float*)d_in[2];
    const float* bq   = (const float*)d_in[3];
    const float* Wk   = (const float*)d_in[4];
    const float* bk   = (const float*)d_in[5];
    const float* Wv   = (const float*)d_in[6];
    const float* bv   = (const float*)d_in[7];
    float* out = (float*)d_out;

    dim3 pg(N_ / 128, E_ / 64, 3 * B_);
    proj_kernel<<<pg, 256>>>(q_in, k_in, Wq, bq, Wk, bk, Wv, bv);

    const int smem_bytes = (64 * 128 * 3 + 128 * 128 + 256) * 4;  // 164864 B
    cudaFuncSetAttribute(attn_kernel,
                         cudaFuncAttributeMaxDynamicSharedMemorySize,
                         smem_bytes);
    dim3 ag(N_ / 128, B_ * NH);
    attn_kernel<<<ag, 512, smem_bytes>>>(out);
}

// round 12
// speedup vs baseline: 2.5205x; 2.5205x over previous
#include <cuda_runtime.h>
#include <cuda_bf16.h>
#include <stdint.h>

#define B_  2
#define C_  512
#define N_  4096
#define E_  512
#define NH  8
#define HD  64

typedef unsigned long long u64;
typedef unsigned int u32;

// bf16 hi/lo split scratch, all [bh][t][d] (rows of 64 bf16 = 128B).
#define QKV_U4 ((size_t)B_ * NH * N_ * HD / 8)
__device__ uint4 g_Qh4[QKV_U4];
__device__ uint4 g_Ql4[QKV_U4];
__device__ uint4 g_Kh4[QKV_U4];
__device__ uint4 g_Kl4[QKV_U4];
__device__ uint4 g_Vh4[QKV_U4];
__device__ uint4 g_Vl4[QKV_U4];

// ---- packed f32x2 helpers (proj) -----------------------------------------
__device__ __forceinline__ u64 bcast2(float x) {
    u64 r; asm("mov.b64 %0, {%1, %1};" : "=l"(r) : "f"(x)); return r;
}
__device__ __forceinline__ float2 unpack2(u64 v) {
    float2 f; asm("mov.b64 {%0, %1}, %2;" : "=f"(f.x), "=f"(f.y) : "l"(v)); return f;
}
__device__ __forceinline__ void fma2(u64& d, u64 a, u64 b) {
    asm("fma.rn.f32x2 %0, %1, %2, %0;" : "+l"(d) : "l"(a), "l"(b));
}

// pack two f32 -> bf16x2: lower 16 bits = a, upper = b
__device__ __forceinline__ u32 pack_bf2(float a, float b) {
    u32 r; asm("cvt.rn.bf16x2.f32 %0, %1, %2;" : "=r"(r) : "f"(b), "f"(a)); return r;
}
__device__ __forceinline__ float lo16f(u32 v) { return __uint_as_float(v << 16); }
__device__ __forceinline__ float hi16f(u32 v) { return __uint_as_float(v & 0xFFFF0000u); }

__device__ __forceinline__ u32 smem_u32(const void* p) {
    u32 a;
    asm("{ .reg .u64 t; cvta.to.shared.u64 t, %1; cvt.u32.u64 %0, t; }" : "=r"(a) : "l"(p));
    return a;
}

// ---- mma.sync / ldmatrix (base PTX ISA, works on sm_103) ------------------
__device__ __forceinline__ void mma16816(float* c, const u32* a, u32 b0, u32 b1) {
    asm volatile(
        "mma.sync.aligned.m16n8k16.row.col.f32.bf16.bf16.f32 "
        "{%0,%1,%2,%3}, {%4,%5,%6,%7}, {%8,%9}, {%0,%1,%2,%3};"
        : "+f"(c[0]), "+f"(c[1]), "+f"(c[2]), "+f"(c[3])
        : "r"(a[0]), "r"(a[1]), "r"(a[2]), "r"(a[3]), "r"(b0), "r"(b1));
}
__device__ __forceinline__ void ldsm4(u32* r, u32 addr) {
    asm volatile("ldmatrix.sync.aligned.m8n8.x4.shared.b16 {%0,%1,%2,%3}, [%4];"
        : "=r"(r[0]), "=r"(r[1]), "=r"(r[2]), "=r"(r[3]) : "r"(addr));
}
__device__ __forceinline__ void ldsm4t(u32* r, u32 addr) {
    asm volatile("ldmatrix.sync.aligned.m8n8.x4.trans.shared.b16 {%0,%1,%2,%3}, [%4];"
        : "=r"(r[0]), "=r"(r[1]), "=r"(r[2]), "=r"(r[3]) : "r"(addr));
}

// ---------------------------------------------------------------------------
// Projection: out[b, t, e] = sum_c X[b, c, t] * W[e, c] + bias[e]
// Emits bf16 hi/lo splits into [bh][t][d] layout.
// ---------------------------------------------------------------------------
__global__ __launch_bounds__(256) void proj_kernel(
    const float* __restrict__ q_in, const float* __restrict__ k_in,
    const float* __restrict__ Wq, const float* __restrict__ bq,
    const float* __restrict__ Wk, const float* __restrict__ bk,
    const float* __restrict__ Wv, const float* __restrict__ bv)
{
    __shared__ float Xs[32 * 128];
    __shared__ float Wt[32 * 65];

    int z = blockIdx.z;
    int proj = z >> 1, b = z & 1;

    const float* X = (proj == 0) ? q_in : k_in;
    const float* W; const float* bias;
    if (proj == 0)      { W = Wq; bias = bq; }
    else if (proj == 1) { W = Wk; bias = bk; }
    else                { W = Wv; bias = bv; }

    int t0 = blockIdx.x * 128;
    int e0 = blockIdx.y * 64;
    int tid = threadIdx.x;
    int tx = tid & 15, ty = tid >> 4;

    u64 acc[4][4];
    #pragma unroll
    for (int p = 0; p < 4; p++)
        #pragma unroll
        for (int j = 0; j < 4; j++) acc[p][j] = 0ull;

    const float* Xb = X + (size_t)b * C_ * N_;

    for (int c0 = 0; c0 < C_; c0 += 32) {
        {   int c = tid >> 5, t4 = (tid & 31) * 4;
            #pragma unroll
            for (int cc = 0; cc < 32; cc += 8)
                *(float4*)&Xs[(c + cc) * 128 + t4] =
                    *(const float4*)&Xb[(size_t)(c0 + c + cc) * N_ + t0 + t4];
        }
        {   int e = tid >> 3, c4 = (tid & 7) * 4;
            #pragma unroll
            for (int ee = 0; ee < 64; ee += 32) {
                float4 w = *(const float4*)&W[(size_t)(e0 + e + ee) * C_ + c0 + c4];
                Wt[(c4 + 0) * 65 + e + ee] = w.x;
                Wt[(c4 + 1) * 65 + e + ee] = w.y;
                Wt[(c4 + 2) * 65 + e + ee] = w.z;
                Wt[(c4 + 3) * 65 + e + ee] = w.w;
            }
        }
        __syncthreads();

        #pragma unroll 4
        for (int c = 0; c < 32; c++) {
            ulonglong2 xa  = *(const ulonglong2*)&Xs[c * 128 + ty * 8];
            ulonglong2 xb2 = *(const ulonglong2*)&Xs[c * 128 + ty * 8 + 4];
            u64 tp[4] = { xa.x, xa.y, xb2.x, xb2.y };
            #pragma unroll
            for (int j = 0; j < 4; j++) {
                u64 wb = bcast2(Wt[c * 65 + tx + 16 * j]);
                #pragma unroll
                for (int p = 0; p < 4; p++) fma2(acc[p][j], tp[p], wb);
            }
        }
        __syncthreads();
    }

    int bh = b * NH + blockIdx.y;
    __nv_bfloat16 *Hh, *Hl;
    if (proj == 0)      { Hh = (__nv_bfloat16*)g_Qh4; Hl = (__nv_bfloat16*)g_Ql4; }
    else if (proj == 1) { Hh = (__nv_bfloat16*)g_Kh4; Hl = (__nv_bfloat16*)g_Kl4; }
    else                { Hh = (__nv_bfloat16*)g_Vh4; Hl = (__nv_bfloat16*)g_Vl4; }

    #pragma unroll
    for (int j = 0; j < 4; j++) {
        int d = tx + 16 * j;
        float bj = bias[e0 + d];
        #pragma unroll
        for (int p = 0; p < 4; p++) {
            float2 f = unpack2(acc[p][j]);
            int t = t0 + ty * 8 + 2 * p;
            float v0 = f.x + bj, v1 = f.y + bj;
            __nv_bfloat16 h0 = __float2bfloat16(v0);
            __nv_bfloat16 h1 = __float2bfloat16(v1);
            size_t i0 = ((size_t)bh * N_ + t) * HD + d;
            Hh[i0]      = h0;
            Hl[i0]      = __float2bfloat16(v0 - __bfloat162float(h0));
            Hh[i0 + HD] = h1;
            Hl[i0 + HD] = __float2bfloat16(v1 - __bfloat162float(h1));
        }
    }
}

// ---------------------------------------------------------------------------
// HMMA flash attention: 128x128 tiles, 8 warps (16 q-rows each),
// mma.sync m16n8k16 bf16 with 3-term compensated splits, no-max softmax.
// Smem (64KB dyn): Kh/Kl/Vh/Vl 16KB each, XOR-swizzled 16B chunks.
// ---------------------------------------------------------------------------
__global__ __launch_bounds__(256) void attn_kernel(float* __restrict__ out)
{
    extern __shared__ char smem[];
    u32 sb = smem_u32(smem);
    const u32 sKH = sb, sKL = sb + 16384, sVH = sb + 32768, sVL = sb + 49152;

    int qtile = (int)gridDim.x - 1 - (int)blockIdx.x;   // heaviest first
    int bh = blockIdx.y;
    int q0 = qtile * 128;
    int tid = threadIdx.x;
    int w = tid >> 5, lane = tid & 31;

    const uint4* Qh4 = g_Qh4 + (size_t)bh * 32768;
    const uint4* Ql4 = g_Ql4 + (size_t)bh * 32768;
    const uint4* Kh4 = g_Kh4 + (size_t)bh * 32768;
    const uint4* Kl4 = g_Kl4 + (size_t)bh * 32768;
    const uint4* Vh4 = g_Vh4 + (size_t)bh * 32768;
    const uint4* Vl4 = g_Vl4 + (size_t)bh * 32768;

    // ---- stage Q tile, load A-fragments once ----
    #pragma unroll
    for (int k = 0; k < 4; k++) {
        int i = tid + 256 * k;
        int r = i >> 3, c = i & 7;
        int off = (r << 7) + ((c ^ (r & 7)) << 4);
        *(uint4*)(smem + off)         = Qh4[(size_t)(q0 + r) * 8 + c];
        *(uint4*)(smem + 16384 + off) = Ql4[(size_t)(q0 + r) * 8 + c];
    }
    __syncthreads();
    u32 qh[4][4], ql[4][4];
    {
        int arow = 16 * w + (lane & 15);
        int asel = lane >> 4;
        #pragma unroll
        for (int ks = 0; ks < 4; ks++) {
            u32 off = (arow << 7) + ((((2 * ks + asel) ^ (arow & 7))) << 4);
            ldsm4(qh[ks], sKH + off);
            ldsm4(ql[ks], sKL + off);
        }
    }

    float oacc[8][4];
    #pragma unroll
    for (int t = 0; t < 8; t++)
        oacc[t][0] = oacc[t][1] = oacc[t][2] = oacc[t][3] = 0.f;
    float lacc0 = 0.f, lacc1 = 0.f;

    int brow = (lane & 7) + ((lane & 16) >> 1);   // S B-frag row-in-16
    int bsel = (lane >> 3) & 1;
    int vrow = lane & 15, vsel = lane >> 4;       // V B-frag (trans)
    int qr0 = q0 + 16 * w + (lane >> 2);

    for (int kt = 0; kt <= qtile; kt++) {
        int k0 = kt * 128;
        __syncthreads();            // prior iteration's smem reads done
        #pragma unroll
        for (int k = 0; k < 4; k++) {
            int i = tid + 256 * k;
            int r = i >> 3, c = i & 7;
            int off = (r << 7) + ((c ^ (r & 7)) << 4);
            size_t gi = (size_t)(k0 + r) * 8 + c;
            *(uint4*)(smem + off)         = Kh4[gi];
            *(uint4*)(smem + 16384 + off) = Kl4[gi];
            *(uint4*)(smem + 32768 + off) = Vh4[gi];
            *(uint4*)(smem + 49152 + off) = Vl4[gi];
        }
        __syncthreads();

        // ---- S = Q K^T (3-term split) ----
        float sacc[16][4];
        #pragma unroll
        for (int t = 0; t < 16; t++)
            sacc[t][0] = sacc[t][1] = sacc[t][2] = sacc[t][3] = 0.f;

        #pragma unroll
        for (int np = 0; np < 8; np++) {
            int rowb = (16 * np + brow) << 7;
            int r7 = brow & 7;
            #pragma unroll
            for (int ks = 0; ks < 4; ks++) {
                u32 off = rowb + (((2 * ks + bsel) ^ r7) << 4);
                u32 kbh[4], kbl[4];
                ldsm4(kbh, sKH + off);
                ldsm4(kbl, sKL + off);
                mma16816(sacc[2 * np],     qh[ks], kbh[0], kbh[1]);
                mma16816(sacc[2 * np],     ql[ks], kbh[0], kbh[1]);
                mma16816(sacc[2 * np],     qh[ks], kbl[0], kbl[1]);
                mma16816(sacc[2 * np + 1], qh[ks], kbh[2], kbh[3]);
                mma16816(sacc[2 * np + 1], ql[ks], kbh[2], kbh[3]);
                mma16816(sacc[2 * np + 1], qh[ks], kbl[2], kbl[3]);
            }
        }

        // ---- softmax (no-max) + PV, fused per k16 chunk ----
        bool diag = (kt == qtile);
        #pragma unroll
        for (int ks = 0; ks < 8; ks++) {
            float* t0 = sacc[2 * ks];
            float* t1 = sacc[2 * ks + 1];
            int cb = k0 + 16 * ks + ((lane & 3) << 1);
            float p00 = __expf(t0[0] * 0.125f), p01 = __expf(t0[1] * 0.125f);
            float p02 = __expf(t0[2] * 0.125f), p03 = __expf(t0[3] * 0.125f);
            float p10 = __expf(t1[0] * 0.125f), p11 = __expf(t1[1] * 0.125f);
            float p12 = __expf(t1[2] * 0.125f), p13 = __expf(t1[3] * 0.125f);
            if (diag) {
                if (cb     > qr0)     p00 = 0.f;
                if (cb + 1 > qr0)     p01 = 0.f;
                if (cb     > qr0 + 8) p02 = 0.f;
                if (cb + 1 > qr0 + 8) p03 = 0.f;
                if (cb + 8 > qr0)     p10 = 0.f;
                if (cb + 9 > qr0)     p11 = 0.f;
                if (cb + 8 > qr0 + 8) p12 = 0.f;
                if (cb + 9 > qr0 + 8) p13 = 0.f;
            }
            lacc0 += p00 + p01 + p10 + p11;
            lacc1 += p02 + p03 + p12 + p13;

            u32 ph[4], pl[4];
            ph[0] = pack_bf2(p00, p01);
            ph[1] = pack_bf2(p02, p03);
            ph[2] = pack_bf2(p10, p11);
            ph[3] = pack_bf2(p12, p13);
            pl[0] = pack_bf2(p00 - lo16f(ph[0]), p01 - hi16f(ph[0]));
            pl[1] = pack_bf2(p02 - lo16f(ph[1]), p03 - hi16f(ph[1]));
            pl[2] = pack_bf2(p10 - lo16f(ph[2]), p11 - hi16f(ph[2]));
            pl[3] = pack_bf2(p12 - lo16f(ph[3]), p13 - hi16f(ph[3]));

            int rvb = (16 * ks + vrow) << 7;
            int vr7 = vrow & 7;
            #pragma unroll
            for (int dp = 0; dp < 4; dp++) {
                u32 off = rvb + (((2 * dp + vsel) ^ vr7) << 4);
                u32 vbh[4], vbl[4];
                ldsm4t(vbh, sVH + off);
                ldsm4t(vbl, sVL + off);
                mma16816(oacc[2 * dp],     ph, vbh[0], vbh[1]);
                mma16816(oacc[2 * dp],     pl, vbh[0], vbh[1]);
                mma16816(oacc[2 * dp],     ph, vbl[0], vbl[1]);
                mma16816(oacc[2 * dp + 1], ph, vbh[2], vbh[3]);
                mma16816(oacc[2 * dp + 1], pl, vbh[2], vbh[3]);
                mma16816(oacc[2 * dp + 1], ph, vbl[2], vbl[3]);
            }
        }
    }

    // ---- epilogue: l reduce (4 lanes), normalize, transpose-stage, store ----
    lacc0 += __shfl_xor_sync(0xffffffffu, lacc0, 1);
    lacc0 += __shfl_xor_sync(0xffffffffu, lacc0, 2);
    lacc1 += __shfl_xor_sync(0xffffffffu, lacc1, 1);
    lacc1 += __shfl_xor_sync(0xffffffffu, lacc1, 2);
    float inv0 = 1.f / lacc0, inv1 = 1.f / lacc1;

    __syncthreads();
    float* Osm = (float*)smem;                    // [q][69] pitch (conflict-free)
    int r = 16 * w + (lane >> 2);
    int dbase = (lane & 3) << 1;
    #pragma unroll
    for (int dt = 0; dt < 8; dt++) {
        int d = dt * 8 + dbase;
        Osm[r * 69 + d]           = oacc[dt][0] * inv0;
        Osm[r * 69 + d + 1]       = oacc[dt][1] * inv0;
        Osm[(r + 8) * 69 + d]     = oacc[dt][2] * inv1;
        Osm[(r + 8) * 69 + d + 1] = oacc[dt][3] * inv1;
    }
    __syncthreads();

    int b = bh >> 3, h = bh & 7;
    float* ob = out + ((size_t)b * E_ + (size_t)h * HD) * N_;
    for (int idx = tid; idx < 64 * 128; idx += 256) {
        int d = idx >> 7, q = idx & 127;
        ob[(size_t)d * N_ + q0 + q] = Osm[q * 69 + d];
    }
}

// ---------------------------------------------------------------------------

extern "C" void kernel_launch(void* const* d_in, const int* in_sizes, int n_in,
                              void* d_out, int out_size)
{
    const float* q_in = (const float*)d_in[0];
    const float* k_in = (const float*)d_in[1];
    const float* Wq   = (const float*)d_in[2];
    const float* bq   = (const float*)d_in[3];
    const float* Wk   = (const float*)d_in[4];
    const float* bk   = (const float*)d_in[5];
    const float* Wv   = (const float*)d_in[6];
    const float* bv   = (const float*)d_in[7];
    float* out = (float*)d_out;

    dim3 pg(N_ / 128, E_ / 64, 3 * B_);
    proj_kernel<<<pg, 256>>>(q_in, k_in, Wq, bq, Wk, bk, Wv, bv);

    const int smem_bytes = 65536;
    cudaFuncSetAttribute(attn_kernel,
                         cudaFuncAttributeMaxDynamicSharedMemorySize, smem_bytes);
    dim3 ag(N_ / 128, B_ * NH);
    attn_kernel<<<ag, 256, smem_bytes>>>(out);
}